// round 9
// baseline (speedup 1.0000x reference)
#include <cuda_runtime.h>
#include <cuda_bf16.h>
#include <math.h>
#include <stdint.h>

// R9: fix accumulator RAW chains in the MMA schedule. R8 showed occupancy
// (12.5%->24%) changed nothing: the 3 same-accumulator split-term MMAs were
// issued back-to-back (asm volatile order), serializing on HMMA latency.
// Now term-major: per k16 step, 16 independent MMAs per split term.
// __launch_bounds__(256,1) for register headroom (no spills).

// Problem constants
#define BT    8
#define LSEQ  8192
#define HID   512
#define PDIM  256
#define MROWS (BT * LSEQ)     // 65536 tokens
#define NCOLS 512             // 2*P (re | im)
#define KDIM  512
#define NCH   64              // scan chunks
#define TCH   128             // steps per chunk
#define NSEQ  (BT * 512)      // 4096 independent real 2-state scans

// GEMM tiling
#define BM 128
#define BN 128
#define BK 32                 // 64 B of bf16 per row -> SW64 swizzle
#define NK (KDIM / BK)        // 16 k-stages

// SMEM: 3 stages x 32KB. Per stage: Ah 8K | Al 8K | Bh 8K | Bl 8K
#define STG_BYTES 32768
#define SM_TOTAL  (3 * STG_BYTES)

// ---------------------------------------------------------------------------
// Static device scratch
// ---------------------------------------------------------------------------
__device__ __nv_bfloat16 g_W1h[KDIM * NCOLS];   // [n][k]
__device__ __nv_bfloat16 g_W1l[KDIM * NCOLS];
__device__ __nv_bfloat16 g_W2h[KDIM * NCOLS];
__device__ __nv_bfloat16 g_W2l[KDIM * NCOLS];
__device__ __nv_bfloat16 g_xh[(size_t)MROWS * NCOLS];
__device__ __nv_bfloat16 g_xl[(size_t)MROWS * NCOLS];
__device__ float g_Bu[(size_t)MROWS * NCOLS];           // 128 MB
__device__ __nv_bfloat16 g_ysh[(size_t)MROWS * NCOLS];  // 64 MB
__device__ __nv_bfloat16 g_ysl[(size_t)MROWS * NCOLS];  // 64 MB
__device__ float g_cf[PDIM * 8];
__device__ float g_mp[PDIM * 4];
__device__ float g_loc1[NCH * NSEQ];
__device__ float g_loc2[NCH * NSEQ];
__device__ float g_car1[NCH * NSEQ];
__device__ float g_car2[NCH * NSEQ];

// ---------------------------------------------------------------------------
// helpers
// ---------------------------------------------------------------------------
__device__ __forceinline__ uint32_t smem_u32(const void* p) {
    uint32_t a;
    asm("{ .reg .u64 t; cvta.to.shared.u64 t, %1; cvt.u32.u64 %0, t; }" : "=r"(a) : "l"(p));
    return a;
}
__device__ __forceinline__ void cp_async16(uint32_t dst, const void* src) {
    asm volatile("cp.async.cg.shared.global [%0], [%1], 16;" :: "r"(dst), "l"(src) : "memory");
}
__device__ __forceinline__ void cp_commit() {
    asm volatile("cp.async.commit_group;" ::: "memory");
}
template <int N>
__device__ __forceinline__ void cp_wait() {
    asm volatile("cp.async.wait_group %0;" :: "n"(N) : "memory");
}
__device__ __forceinline__ void ldsm_x4(uint32_t* r, uint32_t addr) {
    asm volatile("ldmatrix.sync.aligned.m8n8.x4.shared.b16 {%0,%1,%2,%3}, [%4];"
                 : "=r"(r[0]), "=r"(r[1]), "=r"(r[2]), "=r"(r[3]) : "r"(addr));
}
__device__ __forceinline__ void mma_bf16(float* c, const uint32_t* a, uint32_t b0, uint32_t b1) {
    asm volatile(
        "mma.sync.aligned.m16n8k16.row.col.f32.bf16.bf16.f32 "
        "{%0,%1,%2,%3}, {%4,%5,%6,%7}, {%8,%9}, {%0,%1,%2,%3};\n"
        : "+f"(c[0]), "+f"(c[1]), "+f"(c[2]), "+f"(c[3])
        : "r"(a[0]), "r"(a[1]), "r"(a[2]), "r"(a[3]), "r"(b0), "r"(b1));
}
__device__ __forceinline__ void split_f32(float v, __nv_bfloat16& hi, __nv_bfloat16& lo) {
    hi = __float2bfloat16(v);
    lo = __float2bfloat16(v - __bfloat162float(hi));
}
__device__ __forceinline__ uint32_t pack_bf16(__nv_bfloat16 a, __nv_bfloat16 b) {
    return (uint32_t)__bfloat16_as_ushort(a) | ((uint32_t)__bfloat16_as_ushort(b) << 16);
}

// ---------------------------------------------------------------------------
// Kernel 0: per-p coefficients + M^TCH
// ---------------------------------------------------------------------------
__global__ void prep_kernel(const float* __restrict__ steps_param,
                            const float* __restrict__ A_param) {
    int p = threadIdx.x;
    float s = 1.0f / (1.0f + expf(-steps_param[p]));
    float a = fmaxf(A_param[p], 0.0f);
    float c12 = -s * a;
    float c21 = s;
    float c22 = 1.0f - s * s * a;
    g_cf[p * 8 + 0] = s;
    g_cf[p * 8 + 1] = s * s;
    g_cf[p * 8 + 2] = c12;
    g_cf[p * 8 + 3] = c21;
    g_cf[p * 8 + 4] = c22;

    float ma = 1.0f, mb = c12, mc = c21, md = c22;
    #pragma unroll
    for (int i = 0; i < 7; i++) {
        float na = ma * ma + mb * mc;
        float nb = ma * mb + mb * md;
        float nc = mc * ma + md * mc;
        float nd = mc * mb + md * md;
        ma = na; mb = nb; mc = nc; md = nd;
    }
    g_mp[p * 4 + 0] = ma;
    g_mp[p * 4 + 1] = mb;
    g_mp[p * 4 + 2] = mc;
    g_mp[p * 4 + 3] = md;
}

// ---------------------------------------------------------------------------
// Kernel 1: pack weights into [n][k] bf16 hi/lo
// ---------------------------------------------------------------------------
__global__ void buildW_kernel(const float* __restrict__ Bp,
                              const float* __restrict__ Cp) {
    int idx = blockIdx.x * 256 + threadIdx.x;   // 0 .. 512*512-1
    {
        int k = idx >> 9;
        int n = idx & 511;
        float v = (n < 256) ? Bp[n * (HID * 2) + k * 2 + 0]
                            : Bp[(n - 256) * (HID * 2) + k * 2 + 1];
        __nv_bfloat16 hi, lo; split_f32(v, hi, lo);
        g_W1h[n * KDIM + k] = hi;
        g_W1l[n * KDIM + k] = lo;
    }
    {
        int k = idx >> 9;
        int n = idx & 511;
        float v = (k < 256) ? Cp[n * (PDIM * 2) + k * 2 + 0]
                            : -Cp[n * (PDIM * 2) + (k - 256) * 2 + 1];
        __nv_bfloat16 hi, lo; split_f32(v, hi, lo);
        g_W2h[n * KDIM + k] = hi;
        g_W2l[n * KDIM + k] = lo;
    }
}

// ---------------------------------------------------------------------------
// Kernel 2: split x into bf16 hi/lo
// ---------------------------------------------------------------------------
__global__ void __launch_bounds__(256) splitX_kernel(const float* __restrict__ x) {
    size_t i = ((size_t)blockIdx.x * 256 + threadIdx.x) << 2;
    float4 v = *(const float4*)(x + i);
    __nv_bfloat16 h0,l0,h1,l1,h2,l2,h3,l3;
    split_f32(v.x, h0, l0); split_f32(v.y, h1, l1);
    split_f32(v.z, h2, l2); split_f32(v.w, h3, l3);
    *(uint2*)(g_xh + i) = make_uint2(pack_bf16(h0, h1), pack_bf16(h2, h3));
    *(uint2*)(g_xl + i) = make_uint2(pack_bf16(l0, l1), pack_bf16(l2, l3));
}

// ---------------------------------------------------------------------------
// mma.sync GEMM, 3-stage cp.async ring, ldmatrix, SW64 swizzle.
// Term-major MMA schedule: per k16 step, 16 independent HMMAs per split term.
// ---------------------------------------------------------------------------
template <int MODE>
__global__ void __launch_bounds__(256, 1)
mma_gemm(float* __restrict__ Cext, const float* __restrict__ xres,
         const float* __restrict__ Dv) {
    extern __shared__ __align__(128) char smem[];
    const uint32_t sb = smem_u32(smem);

    const __nv_bfloat16* Ah = (MODE == 0) ? g_xh : g_ysh;
    const __nv_bfloat16* Al = (MODE == 0) ? g_xl : g_ysl;
    const __nv_bfloat16* Wh = (MODE == 0) ? g_W1h : g_W2h;
    const __nv_bfloat16* Wl = (MODE == 0) ? g_W1l : g_W2l;
    float* Cout = (MODE == 0) ? g_Bu : Cext;

    const int tid  = threadIdx.x;
    const int lane = tid & 31;
    const int wid  = tid >> 5;
    const int warp_m = wid & 1;        // 0..1 -> 64 rows
    const int warp_n = wid >> 1;       // 0..3 -> 32 cols
    const int mBase = blockIdx.y << 7;
    const int nBase = blockIdx.x << 7;

    // ldmatrix lane mapping
    const int rl   = (lane & 7) + ((lane >> 3) & 1) * 8;
    const int kq16 = (lane >> 4) << 4;

    uint32_t aOff[4], aXor[4];
    #pragma unroll
    for (int mt = 0; mt < 4; mt++) {
        int row = warp_m * 64 + mt * 16 + rl;
        aOff[mt] = row << 6;
        aXor[mt] = (row & 6) << 3;      // SW64: d ^ ((d>>3)&0x30)
    }
    uint32_t bOff[2], bXor[2];
    #pragma unroll
    for (int g = 0; g < 2; g++) {
        int row = warp_n * 32 + g * 16 + rl;
        bOff[g] = row << 6;
        bXor[g] = (row & 6) << 3;
    }

    float c[4][4][4];
    #pragma unroll
    for (int mt = 0; mt < 4; mt++)
        #pragma unroll
        for (int nt = 0; nt < 4; nt++)
            #pragma unroll
            for (int r = 0; r < 4; r++) c[mt][nt][r] = 0.0f;

    // ---- stage loader ----
    auto load_stage = [&](int kc, int buf) {
        const uint32_t s0 = sb + buf * STG_BYTES;
        const int k0 = kc * BK;
        #pragma unroll
        for (int it = 0; it < 8; it++) {
            int lin = tid + (it << 8);
            int mat = lin >> 9;
            int l2  = lin & 511;
            int r   = l2 >> 2;
            int s   = l2 & 3;
            uint32_t d = (r << 6) + (s << 4);
            d ^= (d >> 3) & 0x30;
            const __nv_bfloat16* src;
            int rowg;
            if (mat == 0)      { src = Ah; rowg = mBase + r; }
            else if (mat == 1) { src = Al; rowg = mBase + r; }
            else if (mat == 2) { src = Wh; rowg = nBase + r; }
            else               { src = Wl; rowg = nBase + r; }
            cp_async16(s0 + mat * 8192 + d, src + (size_t)rowg * KDIM + k0 + (s << 3));
        }
        cp_commit();
    };

    load_stage(0, 0);
    load_stage(1, 1);

    int buf = 0;
    for (int kc = 0; kc < NK; kc++) {
        cp_wait<1>();
        __syncthreads();

        if (kc + 2 < NK) {
            int nb = buf + 2; if (nb >= 3) nb -= 3;
            load_stage(kc + 2, nb);
        } else {
            cp_commit();
        }

        const uint32_t s0 = sb + buf * STG_BYTES;
        const uint32_t aHi = s0, aLo = s0 + 8192, bHi = s0 + 16384, bLo = s0 + 24576;

        #pragma unroll
        for (int ks = 0; ks < 2; ks++) {
            const uint32_t kb = (ks << 5) + kq16;
            uint32_t ah[4][4], al[4][4], bh[2][4], bl[2][4];
            #pragma unroll
            for (int mt = 0; mt < 4; mt++) {
                ldsm_x4(ah[mt], aHi + aOff[mt] + (kb ^ aXor[mt]));
                ldsm_x4(al[mt], aLo + aOff[mt] + (kb ^ aXor[mt]));
            }
            #pragma unroll
            for (int g = 0; g < 2; g++) {
                ldsm_x4(bh[g], bHi + bOff[g] + (kb ^ bXor[g]));
                ldsm_x4(bl[g], bLo + bOff[g] + (kb ^ bXor[g]));
            }
            // term hh: 16 independent accumulators
            #pragma unroll
            for (int g = 0; g < 2; g++)
                #pragma unroll
                for (int n2 = 0; n2 < 2; n2++)
                    #pragma unroll
                    for (int mt = 0; mt < 4; mt++)
                        mma_bf16(c[mt][g * 2 + n2], ah[mt], bh[g][n2], bh[g][n2 + 2]);
            // term hl
            #pragma unroll
            for (int g = 0; g < 2; g++)
                #pragma unroll
                for (int n2 = 0; n2 < 2; n2++)
                    #pragma unroll
                    for (int mt = 0; mt < 4; mt++)
                        mma_bf16(c[mt][g * 2 + n2], ah[mt], bl[g][n2], bl[g][n2 + 2]);
            // term lh
            #pragma unroll
            for (int g = 0; g < 2; g++)
                #pragma unroll
                for (int n2 = 0; n2 < 2; n2++)
                    #pragma unroll
                    for (int mt = 0; mt < 4; mt++)
                        mma_bf16(c[mt][g * 2 + n2], al[mt], bh[g][n2], bh[g][n2 + 2]);
        }
        if (++buf == 3) buf = 0;
    }

    // ---- epilogue ----
    const int grp = lane >> 2;
    const int tig = lane & 3;
    #pragma unroll
    for (int nt = 0; nt < 4; nt++) {
        int col = nBase + warp_n * 32 + nt * 8 + (tig << 1);
        float2 d;
        if (MODE == 1) d = *(const float2*)(Dv + col);
        #pragma unroll
        for (int mt = 0; mt < 4; mt++) {
            int row0 = mBase + warp_m * 64 + mt * 16 + grp;
            size_t o0 = (size_t)row0 * NCOLS + col;
            size_t o1 = o0 + ((size_t)8 * NCOLS);
            float2 v0 = make_float2(c[mt][nt][0], c[mt][nt][1]);
            float2 v1 = make_float2(c[mt][nt][2], c[mt][nt][3]);
            if (MODE == 1) {
                float2 x0 = *(const float2*)(xres + o0);
                float2 x1 = *(const float2*)(xres + o1);
                v0.x += d.x * x0.x; v0.y += d.y * x0.y;
                v1.x += d.x * x1.x; v1.y += d.y * x1.y;
            }
            *(float2*)(Cout + o0) = v0;
            *(float2*)(Cout + o1) = v1;
        }
    }
}

// ---------------------------------------------------------------------------
// Scan pass 1: chunk-local scans with zero init; store final (z1,z2)
// ---------------------------------------------------------------------------
__global__ void __launch_bounds__(256) scan_pass1() {
    int c = blockIdx.x, b = blockIdx.y, z = blockIdx.z;
    int p = threadIdx.x;
    int n = (z << 8) + p;
    int sid = (b << 9) + n;

    float s1  = g_cf[p * 8 + 0];
    float s2  = g_cf[p * 8 + 1];
    float c12 = g_cf[p * 8 + 2];
    float c21 = g_cf[p * 8 + 3];
    float c22 = g_cf[p * 8 + 4];

    size_t base = ((size_t)(b * LSEQ + c * TCH) << 9) + n;
    float z1 = 0.0f, z2 = 0.0f;
    #pragma unroll 8
    for (int i = 0; i < TCH; i++) {
        float bu = g_Bu[base + ((size_t)i << 9)];
        float nz1 = fmaf(c12, z2, fmaf(s1, bu, z1));
        float nz2 = fmaf(c21, z1, fmaf(c22, z2, s2 * bu));
        z1 = nz1; z2 = nz2;
    }
    g_loc1[c * NSEQ + sid] = z1;
    g_loc2[c * NSEQ + sid] = z2;
}

// ---------------------------------------------------------------------------
// Scan pass 2: sequential carry scan across chunks (exclusive carries)
// ---------------------------------------------------------------------------
__global__ void __launch_bounds__(256) scan_pass2() {
    int sid = blockIdx.x * 256 + threadIdx.x;   // 0..4095
    int p = sid & 255;
    float m11 = g_mp[p * 4 + 0];
    float m12 = g_mp[p * 4 + 1];
    float m21 = g_mp[p * 4 + 2];
    float m22 = g_mp[p * 4 + 3];

    float c1 = 0.0f, c2 = 0.0f;
    for (int c = 0; c < NCH; c++) {
        g_car1[c * NSEQ + sid] = c1;
        g_car2[c * NSEQ + sid] = c2;
        float l1 = g_loc1[c * NSEQ + sid];
        float l2 = g_loc2[c * NSEQ + sid];
        float n1 = fmaf(m11, c1, fmaf(m12, c2, l1));
        float n2 = fmaf(m21, c1, fmaf(m22, c2, l2));
        c1 = n1; c2 = n2;
    }
}

// ---------------------------------------------------------------------------
// Scan pass 3: replay with carry-in, emit ys split to bf16 hi/lo
// ---------------------------------------------------------------------------
__global__ void __launch_bounds__(256) scan_pass3() {
    int c = blockIdx.x, b = blockIdx.y, z = blockIdx.z;
    int p = threadIdx.x;
    int n = (z << 8) + p;
    int sid = (b << 9) + n;

    float s1  = g_cf[p * 8 + 0];
    float s2  = g_cf[p * 8 + 1];
    float c12 = g_cf[p * 8 + 2];
    float c21 = g_cf[p * 8 + 3];
    float c22 = g_cf[p * 8 + 4];

    size_t base = ((size_t)(b * LSEQ + c * TCH) << 9) + n;
    float z1 = g_car1[c * NSEQ + sid];
    float z2 = g_car2[c * NSEQ + sid];
    #pragma unroll 8
    for (int i = 0; i < TCH; i++) {
        float bu = g_Bu[base + ((size_t)i << 9)];
        float nz1 = fmaf(c12, z2, fmaf(s1, bu, z1));
        float nz2 = fmaf(c21, z1, fmaf(c22, z2, s2 * bu));
        z1 = nz1; z2 = nz2;
        __nv_bfloat16 hi, lo; split_f32(z2, hi, lo);
        g_ysh[base + ((size_t)i << 9)] = hi;
        g_ysl[base + ((size_t)i << 9)] = lo;
    }
}

// ---------------------------------------------------------------------------
// Launch
// ---------------------------------------------------------------------------
extern "C" void kernel_launch(void* const* d_in, const int* in_sizes, int n_in,
                              void* d_out, int out_size) {
    const float* x  = (const float*)d_in[0];   // (8, 8192, 512)
    const float* sp = (const float*)d_in[1];   // (256,)
    const float* Ap = (const float*)d_in[2];   // (256,)
    const float* Bp = (const float*)d_in[3];   // (256, 512, 2)
    const float* Cp = (const float*)d_in[4];   // (512, 256, 2)
    const float* Dp = (const float*)d_in[5];   // (512,)
    float* y = (float*)d_out;                  // (8, 8192, 512)

    cudaFuncSetAttribute(mma_gemm<0>, cudaFuncAttributeMaxDynamicSharedMemorySize, SM_TOTAL);
    cudaFuncSetAttribute(mma_gemm<1>, cudaFuncAttributeMaxDynamicSharedMemorySize, SM_TOTAL);

    prep_kernel<<<1, 256>>>(sp, Ap);
    buildW_kernel<<<1024, 256>>>(Bp, Cp);
    splitX_kernel<<<(MROWS * NCOLS) / 1024, 256>>>(x);

    // GEMM1: Bu = x @ W1
    mma_gemm<0><<<dim3(NCOLS / BN, MROWS / BM), 256, SM_TOTAL>>>(nullptr, nullptr, nullptr);

    // Chunked linear scan (pass3 emits ys as bf16 hi/lo)
    scan_pass1<<<dim3(NCH, BT, 2), 256>>>();
    scan_pass2<<<16, 256>>>();
    scan_pass3<<<dim3(NCH, BT, 2), 256>>>();

    // GEMM2 + epilogue: y = ys @ W2 + D .* x
    mma_gemm<1><<<dim3(NCOLS / BN, MROWS / BM), 256, SM_TOTAL>>>(y, x, Dp);
}

// round 12
// speedup vs baseline: 1.4063x; 1.4063x over previous
#include <cuda_runtime.h>
#include <cuda_bf16.h>
#include <cuda_fp16.h>
#include <math.h>
#include <stdint.h>

// R12: third submission of the 2-term fp16 design (R10/R11 died to the
// recurring brokered-container flake; source re-audited twice vs the
// R9 kernel that ran — same pipeline skeleton, same instruction families,
// all sm_100-legal; R2->R3 precedent: identical resubmit passed).
//
// Design: activations exact fp16 hi+lo, weights single fp16 (error ~ weight
// rounding ~3e-4 RMS vs 1e-3 budget). 3-stage cp.async ring, SW64 swizzle,
// 2 CTAs/SM. 2/3 the MMA count of the bf16 3-term path whose ceiling was
// ~330us/GEMM across R7/R8/R9.

// Problem constants
#define BT    8
#define LSEQ  8192
#define HID   512
#define PDIM  256
#define MROWS (BT * LSEQ)     // 65536 tokens
#define NCOLS 512             // 2*P (re | im)
#define KDIM  512
#define NCH   64              // scan chunks
#define TCH   128             // steps per chunk
#define NSEQ  (BT * 512)      // 4096 independent real 2-state scans

// GEMM tiling
#define BM 128
#define BN 128
#define BK 32                 // 64 B of fp16 per row -> SW64 swizzle
#define NK (KDIM / BK)        // 16 k-stages

// SMEM: 3 stages x 24KB. Per stage: Ah 8K | Al 8K | Wf 8K
#define STG_BYTES 24576
#define SM_TOTAL  (3 * STG_BYTES)

// ---------------------------------------------------------------------------
// Static device scratch
// ---------------------------------------------------------------------------
__device__ __half g_W1f[KDIM * NCOLS];          // [n][k] single fp16
__device__ __half g_W2f[KDIM * NCOLS];
__device__ __half g_xh[(size_t)MROWS * NCOLS];  // x split hi (fp16)
__device__ __half g_xl[(size_t)MROWS * NCOLS];  // x split lo (fp16)
__device__ float g_Bu[(size_t)MROWS * NCOLS];   // 128 MB
__device__ __half g_ysh[(size_t)MROWS * NCOLS]; // 64 MB
__device__ __half g_ysl[(size_t)MROWS * NCOLS]; // 64 MB
__device__ float g_cf[PDIM * 8];
__device__ float g_mp[PDIM * 4];
__device__ float g_loc1[NCH * NSEQ];
__device__ float g_loc2[NCH * NSEQ];
__device__ float g_car1[NCH * NSEQ];
__device__ float g_car2[NCH * NSEQ];

// ---------------------------------------------------------------------------
// helpers
// ---------------------------------------------------------------------------
__device__ __forceinline__ uint32_t smem_u32(const void* p) {
    uint32_t a;
    asm("{ .reg .u64 t; cvta.to.shared.u64 t, %1; cvt.u32.u64 %0, t; }" : "=r"(a) : "l"(p));
    return a;
}
__device__ __forceinline__ void cp_async16(uint32_t dst, const void* src) {
    asm volatile("cp.async.cg.shared.global [%0], [%1], 16;" :: "r"(dst), "l"(src) : "memory");
}
__device__ __forceinline__ void cp_commit() {
    asm volatile("cp.async.commit_group;" ::: "memory");
}
template <int N>
__device__ __forceinline__ void cp_wait() {
    asm volatile("cp.async.wait_group %0;" :: "n"(N) : "memory");
}
__device__ __forceinline__ void ldsm_x4(uint32_t* r, uint32_t addr) {
    asm volatile("ldmatrix.sync.aligned.m8n8.x4.shared.b16 {%0,%1,%2,%3}, [%4];"
                 : "=r"(r[0]), "=r"(r[1]), "=r"(r[2]), "=r"(r[3]) : "r"(addr));
}
__device__ __forceinline__ void mma_f16(float* c, const uint32_t* a, uint32_t b0, uint32_t b1) {
    asm volatile(
        "mma.sync.aligned.m16n8k16.row.col.f32.f16.f16.f32 "
        "{%0,%1,%2,%3}, {%4,%5,%6,%7}, {%8,%9}, {%0,%1,%2,%3};\n"
        : "+f"(c[0]), "+f"(c[1]), "+f"(c[2]), "+f"(c[3])
        : "r"(a[0]), "r"(a[1]), "r"(a[2]), "r"(a[3]), "r"(b0), "r"(b1));
}
__device__ __forceinline__ void split_f32h(float v, __half& hi, __half& lo) {
    hi = __float2half(v);
    lo = __float2half(v - __half2float(hi));
}
__device__ __forceinline__ uint32_t pack_h(__half a, __half b) {
    return (uint32_t)__half_as_ushort(a) | ((uint32_t)__half_as_ushort(b) << 16);
}

// ---------------------------------------------------------------------------
// Kernel 0: per-p coefficients + M^TCH
// ---------------------------------------------------------------------------
__global__ void prep_kernel(const float* __restrict__ steps_param,
                            const float* __restrict__ A_param) {
    int p = threadIdx.x;
    float s = 1.0f / (1.0f + expf(-steps_param[p]));
    float a = fmaxf(A_param[p], 0.0f);
    float c12 = -s * a;
    float c21 = s;
    float c22 = 1.0f - s * s * a;
    g_cf[p * 8 + 0] = s;
    g_cf[p * 8 + 1] = s * s;
    g_cf[p * 8 + 2] = c12;
    g_cf[p * 8 + 3] = c21;
    g_cf[p * 8 + 4] = c22;

    float ma = 1.0f, mb = c12, mc = c21, md = c22;
    #pragma unroll
    for (int i = 0; i < 7; i++) {
        float na = ma * ma + mb * mc;
        float nb = ma * mb + mb * md;
        float nc = mc * ma + md * mc;
        float nd = mc * mb + md * md;
        ma = na; mb = nb; mc = nc; md = nd;
    }
    g_mp[p * 4 + 0] = ma;
    g_mp[p * 4 + 1] = mb;
    g_mp[p * 4 + 2] = mc;
    g_mp[p * 4 + 3] = md;
}

// ---------------------------------------------------------------------------
// Kernel 1: pack weights into [n][k] single fp16
// ---------------------------------------------------------------------------
__global__ void buildW_kernel(const float* __restrict__ Bp,
                              const float* __restrict__ Cp) {
    int idx = blockIdx.x * 256 + threadIdx.x;   // 0 .. 512*512-1
    {
        int k = idx >> 9;
        int n = idx & 511;
        float v = (n < 256) ? Bp[n * (HID * 2) + k * 2 + 0]
                            : Bp[(n - 256) * (HID * 2) + k * 2 + 1];
        g_W1f[n * KDIM + k] = __float2half(v);
    }
    {
        int k = idx >> 9;
        int n = idx & 511;
        float v = (k < 256) ? Cp[n * (PDIM * 2) + k * 2 + 0]
                            : -Cp[n * (PDIM * 2) + (k - 256) * 2 + 1];
        g_W2f[n * KDIM + k] = __float2half(v);
    }
}

// ---------------------------------------------------------------------------
// Kernel 2: split x into fp16 hi/lo
// ---------------------------------------------------------------------------
__global__ void __launch_bounds__(256) splitX_kernel(const float* __restrict__ x) {
    size_t i = ((size_t)blockIdx.x * 256 + threadIdx.x) << 2;
    float4 v = *(const float4*)(x + i);
    __half h0,l0,h1,l1,h2,l2,h3,l3;
    split_f32h(v.x, h0, l0); split_f32h(v.y, h1, l1);
    split_f32h(v.z, h2, l2); split_f32h(v.w, h3, l3);
    *(uint2*)(g_xh + i) = make_uint2(pack_h(h0, h1), pack_h(h2, h3));
    *(uint2*)(g_xl + i) = make_uint2(pack_h(l0, l1), pack_h(l2, l3));
}

// ---------------------------------------------------------------------------
// mma.sync fp16 GEMM, 2-term split, 3-stage cp.async ring, SW64, ldmatrix.
// 128x128 block, K stages of 32, 256 thr = 8 warps (2m x 4n), warp 64x32.
// ---------------------------------------------------------------------------
template <int MODE>
__global__ void __launch_bounds__(256, 2)
mma_gemm(float* __restrict__ Cext, const float* __restrict__ xres,
         const float* __restrict__ Dv) {
    extern __shared__ __align__(128) char smem[];
    const uint32_t sb = smem_u32(smem);

    const __half* Ah = (MODE == 0) ? g_xh : g_ysh;
    const __half* Al = (MODE == 0) ? g_xl : g_ysl;
    const __half* Wf = (MODE == 0) ? g_W1f : g_W2f;
    float* Cout = (MODE == 0) ? g_Bu : Cext;

    const int tid  = threadIdx.x;
    const int lane = tid & 31;
    const int wid  = tid >> 5;
    const int warp_m = wid & 1;        // 0..1 -> 64 rows
    const int warp_n = wid >> 1;       // 0..3 -> 32 cols
    const int mBase = blockIdx.y << 7;
    const int nBase = blockIdx.x << 7;

    // ldmatrix lane mapping
    const int rl   = (lane & 7) + ((lane >> 3) & 1) * 8;
    const int kq16 = (lane >> 4) << 4;

    uint32_t aOff[4], aXor[4];
    #pragma unroll
    for (int mt = 0; mt < 4; mt++) {
        int row = warp_m * 64 + mt * 16 + rl;
        aOff[mt] = row << 6;
        aXor[mt] = (row & 6) << 3;      // SW64: d ^ ((d>>3)&0x30)
    }
    uint32_t bOff[2], bXor[2];
    #pragma unroll
    for (int g = 0; g < 2; g++) {
        int row = warp_n * 32 + g * 16 + rl;
        bOff[g] = row << 6;
        bXor[g] = (row & 6) << 3;
    }

    float c[4][4][4];
    #pragma unroll
    for (int mt = 0; mt < 4; mt++)
        #pragma unroll
        for (int nt = 0; nt < 4; nt++)
            #pragma unroll
            for (int r = 0; r < 4; r++) c[mt][nt][r] = 0.0f;

    // ---- stage loader: 3 matrices x 128 rows x 4 segs(16B) = 1536 cp.async ----
    auto load_stage = [&](int kc, int buf) {
        const uint32_t s0 = sb + buf * STG_BYTES;
        const int k0 = kc * BK;
        #pragma unroll
        for (int it = 0; it < 6; it++) {
            int lin = tid + (it << 8);     // 0..1535
            int mat = lin >> 9;            // constant per it
            int l2  = lin & 511;
            int r   = l2 >> 2;
            int s   = l2 & 3;
            uint32_t d = (r << 6) + (s << 4);
            d ^= (d >> 3) & 0x30;
            const __half* src;
            int rowg;
            if (mat == 0)      { src = Ah; rowg = mBase + r; }
            else if (mat == 1) { src = Al; rowg = mBase + r; }
            else               { src = Wf; rowg = nBase + r; }
            cp_async16(s0 + mat * 8192 + d, src + (size_t)rowg * KDIM + k0 + (s << 3));
        }
        cp_commit();
    };

    load_stage(0, 0);
    load_stage(1, 1);

    int buf = 0;
    for (int kc = 0; kc < NK; kc++) {
        cp_wait<1>();
        __syncthreads();

        if (kc + 2 < NK) {
            int nb = buf + 2; if (nb >= 3) nb -= 3;
            load_stage(kc + 2, nb);
        } else {
            cp_commit();
        }

        const uint32_t s0 = sb + buf * STG_BYTES;
        const uint32_t aHi = s0, aLo = s0 + 8192, bFf = s0 + 16384;

        #pragma unroll
        for (int ks = 0; ks < 2; ks++) {
            const uint32_t kb = (ks << 5) + kq16;
            uint32_t ah[4][4], al[4][4];
            #pragma unroll
            for (int mt = 0; mt < 4; mt++) {
                ldsm_x4(ah[mt], aHi + aOff[mt] + (kb ^ aXor[mt]));
                ldsm_x4(al[mt], aLo + aOff[mt] + (kb ^ aXor[mt]));
            }
            #pragma unroll
            for (int g = 0; g < 2; g++) {
                uint32_t bf[4];
                ldsm_x4(bf, bFf + bOff[g] + (kb ^ bXor[g]));
                #pragma unroll
                for (int n2 = 0; n2 < 2; n2++) {
                    const int nt = g * 2 + n2;
                    const uint32_t b0 = bf[n2], b1 = bf[n2 + 2];
                    #pragma unroll
                    for (int mt = 0; mt < 4; mt++) {
                        float* cc = c[mt][nt];
                        mma_f16(cc, ah[mt], b0, b1);
                        mma_f16(cc, al[mt], b0, b1);
                    }
                }
            }
        }
        if (++buf == 3) buf = 0;
    }

    // ---- epilogue ----
    const int grp = lane >> 2;
    const int tig = lane & 3;
    #pragma unroll
    for (int nt = 0; nt < 4; nt++) {
        int col = nBase + warp_n * 32 + nt * 8 + (tig << 1);
        float2 d;
        if (MODE == 1) d = *(const float2*)(Dv + col);
        #pragma unroll
        for (int mt = 0; mt < 4; mt++) {
            int row0 = mBase + warp_m * 64 + mt * 16 + grp;
            size_t o0 = (size_t)row0 * NCOLS + col;
            size_t o1 = o0 + ((size_t)8 * NCOLS);
            float2 v0 = make_float2(c[mt][nt][0], c[mt][nt][1]);
            float2 v1 = make_float2(c[mt][nt][2], c[mt][nt][3]);
            if (MODE == 1) {
                float2 x0 = *(const float2*)(xres + o0);
                float2 x1 = *(const float2*)(xres + o1);
                v0.x += d.x * x0.x; v0.y += d.y * x0.y;
                v1.x += d.x * x1.x; v1.y += d.y * x1.y;
            }
            *(float2*)(Cout + o0) = v0;
            *(float2*)(Cout + o1) = v1;
        }
    }
}

// ---------------------------------------------------------------------------
// Scan pass 1: chunk-local scans with zero init; store final (z1,z2)
// ---------------------------------------------------------------------------
__global__ void __launch_bounds__(256) scan_pass1() {
    int c = blockIdx.x, b = blockIdx.y, z = blockIdx.z;
    int p = threadIdx.x;
    int n = (z << 8) + p;
    int sid = (b << 9) + n;

    float s1  = g_cf[p * 8 + 0];
    float s2  = g_cf[p * 8 + 1];
    float c12 = g_cf[p * 8 + 2];
    float c21 = g_cf[p * 8 + 3];
    float c22 = g_cf[p * 8 + 4];

    size_t base = ((size_t)(b * LSEQ + c * TCH) << 9) + n;
    float z1 = 0.0f, z2 = 0.0f;
    #pragma unroll 8
    for (int i = 0; i < TCH; i++) {
        float bu = g_Bu[base + ((size_t)i << 9)];
        float nz1 = fmaf(c12, z2, fmaf(s1, bu, z1));
        float nz2 = fmaf(c21, z1, fmaf(c22, z2, s2 * bu));
        z1 = nz1; z2 = nz2;
    }
    g_loc1[c * NSEQ + sid] = z1;
    g_loc2[c * NSEQ + sid] = z2;
}

// ---------------------------------------------------------------------------
// Scan pass 2: sequential carry scan across chunks (exclusive carries)
// ---------------------------------------------------------------------------
__global__ void __launch_bounds__(256) scan_pass2() {
    int sid = blockIdx.x * 256 + threadIdx.x;   // 0..4095
    int p = sid & 255;
    float m11 = g_mp[p * 4 + 0];
    float m12 = g_mp[p * 4 + 1];
    float m21 = g_mp[p * 4 + 2];
    float m22 = g_mp[p * 4 + 3];

    float c1 = 0.0f, c2 = 0.0f;
    for (int c = 0; c < NCH; c++) {
        g_car1[c * NSEQ + sid] = c1;
        g_car2[c * NSEQ + sid] = c2;
        float l1 = g_loc1[c * NSEQ + sid];
        float l2 = g_loc2[c * NSEQ + sid];
        float n1 = fmaf(m11, c1, fmaf(m12, c2, l1));
        float n2 = fmaf(m21, c1, fmaf(m22, c2, l2));
        c1 = n1; c2 = n2;
    }
}

// ---------------------------------------------------------------------------
// Scan pass 3: replay with carry-in, emit ys split to fp16 hi/lo
// ---------------------------------------------------------------------------
__global__ void __launch_bounds__(256) scan_pass3() {
    int c = blockIdx.x, b = blockIdx.y, z = blockIdx.z;
    int p = threadIdx.x;
    int n = (z << 8) + p;
    int sid = (b << 9) + n;

    float s1  = g_cf[p * 8 + 0];
    float s2  = g_cf[p * 8 + 1];
    float c12 = g_cf[p * 8 + 2];
    float c21 = g_cf[p * 8 + 3];
    float c22 = g_cf[p * 8 + 4];

    size_t base = ((size_t)(b * LSEQ + c * TCH) << 9) + n;
    float z1 = g_car1[c * NSEQ + sid];
    float z2 = g_car2[c * NSEQ + sid];
    #pragma unroll 8
    for (int i = 0; i < TCH; i++) {
        float bu = g_Bu[base + ((size_t)i << 9)];
        float nz1 = fmaf(c12, z2, fmaf(s1, bu, z1));
        float nz2 = fmaf(c21, z1, fmaf(c22, z2, s2 * bu));
        z1 = nz1; z2 = nz2;
        __half hi, lo; split_f32h(z2, hi, lo);
        g_ysh[base + ((size_t)i << 9)] = hi;
        g_ysl[base + ((size_t)i << 9)] = lo;
    }
}

// ---------------------------------------------------------------------------
// Launch
// ---------------------------------------------------------------------------
extern "C" void kernel_launch(void* const* d_in, const int* in_sizes, int n_in,
                              void* d_out, int out_size) {
    const float* x  = (const float*)d_in[0];   // (8, 8192, 512)
    const float* sp = (const float*)d_in[1];   // (256,)
    const float* Ap = (const float*)d_in[2];   // (256,)
    const float* Bp = (const float*)d_in[3];   // (256, 512, 2)
    const float* Cp = (const float*)d_in[4];   // (512, 256, 2)
    const float* Dp = (const float*)d_in[5];   // (512,)
    float* y = (float*)d_out;                  // (8, 8192, 512)

    cudaFuncSetAttribute(mma_gemm<0>, cudaFuncAttributeMaxDynamicSharedMemorySize, SM_TOTAL);
    cudaFuncSetAttribute(mma_gemm<1>, cudaFuncAttributeMaxDynamicSharedMemorySize, SM_TOTAL);

    prep_kernel<<<1, 256>>>(sp, Ap);
    buildW_kernel<<<1024, 256>>>(Bp, Cp);
    splitX_kernel<<<(MROWS * NCOLS) / 1024, 256>>>(x);

    // GEMM1: Bu = x @ W1
    mma_gemm<0><<<dim3(NCOLS / BN, MROWS / BM), 256, SM_TOTAL>>>(nullptr, nullptr, nullptr);

    // Chunked linear scan (pass3 emits ys as fp16 hi/lo)
    scan_pass1<<<dim3(NCH, BT, 2), 256>>>();
    scan_pass2<<<16, 256>>>();
    scan_pass3<<<dim3(NCH, BT, 2), 256>>>();

    // GEMM2 + epilogue: y = ys @ W2 + D .* x
    mma_gemm<1><<<dim3(NCOLS / BN, MROWS / BM), 256, SM_TOTAL>>>(y, x, Dp);
}

// round 13
// speedup vs baseline: 2.0767x; 1.4768x over previous
#include <cuda_runtime.h>
#include <cuda_bf16.h>
#include <cuda_fp16.h>
#include <math.h>
#include <stdint.h>

// R13: single-fp16 x single-fp16 GEMMs (1 MMA/tile; R12's confirmed model:
// GEMM time ~ MMA count against a schedule-invariant ceiling). Error adds
// activation-rounding ~ sqrt(2)x R12's 2.93e-4 -> ~4.1e-4 vs 1e-3 budget
// (deterministic fixed-seed inputs). Fallback if >=7e-4: revert to 2-term.
// Keeps: 3-stage cp.async ring, SW64 swizzle, 2 CTAs/SM, ldmatrix.

// Problem constants
#define BT    8
#define LSEQ  8192
#define HID   512
#define PDIM  256
#define MROWS (BT * LSEQ)     // 65536 tokens
#define NCOLS 512             // 2*P (re | im)
#define KDIM  512
#define NCH   64              // scan chunks
#define TCH   128             // steps per chunk
#define NSEQ  (BT * 512)      // 4096 independent real 2-state scans

// GEMM tiling
#define BM 128
#define BN 128
#define BK 32                 // 64 B of fp16 per row -> SW64 swizzle
#define NK (KDIM / BK)        // 16 k-stages

// SMEM: 3 stages x 16KB. Per stage: Af 8K | Wf 8K
#define STG_BYTES 16384
#define SM_TOTAL  (3 * STG_BYTES)

// ---------------------------------------------------------------------------
// Static device scratch
// ---------------------------------------------------------------------------
__device__ __half g_W1f[KDIM * NCOLS];          // [n][k] fp16
__device__ __half g_W2f[KDIM * NCOLS];
__device__ __half g_xf[(size_t)MROWS * NCOLS];  // x fp16
__device__ float g_Bu[(size_t)MROWS * NCOLS];   // 128 MB
__device__ __half g_ysf[(size_t)MROWS * NCOLS]; // 64 MB
__device__ float g_cf[PDIM * 8];
__device__ float g_mp[PDIM * 4];
__device__ float g_loc1[NCH * NSEQ];
__device__ float g_loc2[NCH * NSEQ];
__device__ float g_car1[NCH * NSEQ];
__device__ float g_car2[NCH * NSEQ];

// ---------------------------------------------------------------------------
// helpers
// ---------------------------------------------------------------------------
__device__ __forceinline__ uint32_t smem_u32(const void* p) {
    uint32_t a;
    asm("{ .reg .u64 t; cvta.to.shared.u64 t, %1; cvt.u32.u64 %0, t; }" : "=r"(a) : "l"(p));
    return a;
}
__device__ __forceinline__ void cp_async16(uint32_t dst, const void* src) {
    asm volatile("cp.async.cg.shared.global [%0], [%1], 16;" :: "r"(dst), "l"(src) : "memory");
}
__device__ __forceinline__ void cp_commit() {
    asm volatile("cp.async.commit_group;" ::: "memory");
}
template <int N>
__device__ __forceinline__ void cp_wait() {
    asm volatile("cp.async.wait_group %0;" :: "n"(N) : "memory");
}
__device__ __forceinline__ void ldsm_x4(uint32_t* r, uint32_t addr) {
    asm volatile("ldmatrix.sync.aligned.m8n8.x4.shared.b16 {%0,%1,%2,%3}, [%4];"
                 : "=r"(r[0]), "=r"(r[1]), "=r"(r[2]), "=r"(r[3]) : "r"(addr));
}
__device__ __forceinline__ void mma_f16(float* c, const uint32_t* a, uint32_t b0, uint32_t b1) {
    asm volatile(
        "mma.sync.aligned.m16n8k16.row.col.f32.f16.f16.f32 "
        "{%0,%1,%2,%3}, {%4,%5,%6,%7}, {%8,%9}, {%0,%1,%2,%3};\n"
        : "+f"(c[0]), "+f"(c[1]), "+f"(c[2]), "+f"(c[3])
        : "r"(a[0]), "r"(a[1]), "r"(a[2]), "r"(a[3]), "r"(b0), "r"(b1));
}
__device__ __forceinline__ uint32_t pack_h(__half a, __half b) {
    return (uint32_t)__half_as_ushort(a) | ((uint32_t)__half_as_ushort(b) << 16);
}

// ---------------------------------------------------------------------------
// Kernel 0: per-p coefficients + M^TCH
// ---------------------------------------------------------------------------
__global__ void prep_kernel(const float* __restrict__ steps_param,
                            const float* __restrict__ A_param) {
    int p = threadIdx.x;
    float s = 1.0f / (1.0f + expf(-steps_param[p]));
    float a = fmaxf(A_param[p], 0.0f);
    float c12 = -s * a;
    float c21 = s;
    float c22 = 1.0f - s * s * a;
    g_cf[p * 8 + 0] = s;
    g_cf[p * 8 + 1] = s * s;
    g_cf[p * 8 + 2] = c12;
    g_cf[p * 8 + 3] = c21;
    g_cf[p * 8 + 4] = c22;

    float ma = 1.0f, mb = c12, mc = c21, md = c22;
    #pragma unroll
    for (int i = 0; i < 7; i++) {
        float na = ma * ma + mb * mc;
        float nb = ma * mb + mb * md;
        float nc = mc * ma + md * mc;
        float nd = mc * mb + md * md;
        ma = na; mb = nb; mc = nc; md = nd;
    }
    g_mp[p * 4 + 0] = ma;
    g_mp[p * 4 + 1] = mb;
    g_mp[p * 4 + 2] = mc;
    g_mp[p * 4 + 3] = md;
}

// ---------------------------------------------------------------------------
// Kernel 1: pack weights into [n][k] fp16
// ---------------------------------------------------------------------------
__global__ void buildW_kernel(const float* __restrict__ Bp,
                              const float* __restrict__ Cp) {
    int idx = blockIdx.x * 256 + threadIdx.x;   // 0 .. 512*512-1
    {
        int k = idx >> 9;
        int n = idx & 511;
        float v = (n < 256) ? Bp[n * (HID * 2) + k * 2 + 0]
                            : Bp[(n - 256) * (HID * 2) + k * 2 + 1];
        g_W1f[n * KDIM + k] = __float2half(v);
    }
    {
        int k = idx >> 9;
        int n = idx & 511;
        float v = (k < 256) ? Cp[n * (PDIM * 2) + k * 2 + 0]
                            : -Cp[n * (PDIM * 2) + (k - 256) * 2 + 1];
        g_W2f[n * KDIM + k] = __float2half(v);
    }
}

// ---------------------------------------------------------------------------
// Kernel 2: convert x to fp16
// ---------------------------------------------------------------------------
__global__ void __launch_bounds__(256) convX_kernel(const float* __restrict__ x) {
    size_t i = ((size_t)blockIdx.x * 256 + threadIdx.x) << 2;
    float4 v = *(const float4*)(x + i);
    *(uint2*)(g_xf + i) = make_uint2(pack_h(__float2half(v.x), __float2half(v.y)),
                                     pack_h(__float2half(v.z), __float2half(v.w)));
}

// ---------------------------------------------------------------------------
// mma.sync fp16 GEMM (single term), 3-stage cp.async ring, SW64, ldmatrix.
// 128x128 block, K stages of 32, 256 thr = 8 warps (2m x 4n), warp 64x32.
// ---------------------------------------------------------------------------
template <int MODE>
__global__ void __launch_bounds__(256, 2)
mma_gemm(float* __restrict__ Cext, const float* __restrict__ xres,
         const float* __restrict__ Dv) {
    extern __shared__ __align__(128) char smem[];
    const uint32_t sb = smem_u32(smem);

    const __half* Af = (MODE == 0) ? g_xf : g_ysf;
    const __half* Wf = (MODE == 0) ? g_W1f : g_W2f;
    float* Cout = (MODE == 0) ? g_Bu : Cext;

    const int tid  = threadIdx.x;
    const int lane = tid & 31;
    const int wid  = tid >> 5;
    const int warp_m = wid & 1;        // 0..1 -> 64 rows
    const int warp_n = wid >> 1;       // 0..3 -> 32 cols
    const int mBase = blockIdx.y << 7;
    const int nBase = blockIdx.x << 7;

    // ldmatrix lane mapping
    const int rl   = (lane & 7) + ((lane >> 3) & 1) * 8;
    const int kq16 = (lane >> 4) << 4;

    uint32_t aOff[4], aXor[4];
    #pragma unroll
    for (int mt = 0; mt < 4; mt++) {
        int row = warp_m * 64 + mt * 16 + rl;
        aOff[mt] = row << 6;
        aXor[mt] = (row & 6) << 3;      // SW64: d ^ ((d>>3)&0x30)
    }
    uint32_t bOff[2], bXor[2];
    #pragma unroll
    for (int g = 0; g < 2; g++) {
        int row = warp_n * 32 + g * 16 + rl;
        bOff[g] = row << 6;
        bXor[g] = (row & 6) << 3;
    }

    float c[4][4][4];
    #pragma unroll
    for (int mt = 0; mt < 4; mt++)
        #pragma unroll
        for (int nt = 0; nt < 4; nt++)
            #pragma unroll
            for (int r = 0; r < 4; r++) c[mt][nt][r] = 0.0f;

    // ---- stage loader: 2 matrices x 128 rows x 4 segs(16B) = 1024 cp.async ----
    auto load_stage = [&](int kc, int buf) {
        const uint32_t s0 = sb + buf * STG_BYTES;
        const int k0 = kc * BK;
        #pragma unroll
        for (int it = 0; it < 4; it++) {
            int lin = tid + (it << 8);     // 0..1023
            int mat = lin >> 9;            // constant per it
            int l2  = lin & 511;
            int r   = l2 >> 2;
            int s   = l2 & 3;
            uint32_t d = (r << 6) + (s << 4);
            d ^= (d >> 3) & 0x30;
            const __half* src = (mat == 0) ? Af : Wf;
            int rowg = ((mat == 0) ? mBase : nBase) + r;
            cp_async16(s0 + mat * 8192 + d, src + (size_t)rowg * KDIM + k0 + (s << 3));
        }
        cp_commit();
    };

    load_stage(0, 0);
    load_stage(1, 1);

    int buf = 0;
    for (int kc = 0; kc < NK; kc++) {
        cp_wait<1>();
        __syncthreads();

        if (kc + 2 < NK) {
            int nb = buf + 2; if (nb >= 3) nb -= 3;
            load_stage(kc + 2, nb);
        } else {
            cp_commit();
        }

        const uint32_t s0 = sb + buf * STG_BYTES;
        const uint32_t aFf = s0, bFf = s0 + 8192;

        #pragma unroll
        for (int ks = 0; ks < 2; ks++) {
            const uint32_t kb = (ks << 5) + kq16;
            uint32_t ah[4][4];
            #pragma unroll
            for (int mt = 0; mt < 4; mt++)
                ldsm_x4(ah[mt], aFf + aOff[mt] + (kb ^ aXor[mt]));
            #pragma unroll
            for (int g = 0; g < 2; g++) {
                uint32_t bf[4];
                ldsm_x4(bf, bFf + bOff[g] + (kb ^ bXor[g]));
                #pragma unroll
                for (int n2 = 0; n2 < 2; n2++) {
                    const int nt = g * 2 + n2;
                    const uint32_t b0 = bf[n2], b1 = bf[n2 + 2];
                    #pragma unroll
                    for (int mt = 0; mt < 4; mt++)
                        mma_f16(c[mt][nt], ah[mt], b0, b1);
                }
            }
        }
        if (++buf == 3) buf = 0;
    }

    // ---- epilogue ----
    const int grp = lane >> 2;
    const int tig = lane & 3;
    #pragma unroll
    for (int nt = 0; nt < 4; nt++) {
        int col = nBase + warp_n * 32 + nt * 8 + (tig << 1);
        float2 d;
        if (MODE == 1) d = *(const float2*)(Dv + col);
        #pragma unroll
        for (int mt = 0; mt < 4; mt++) {
            int row0 = mBase + warp_m * 64 + mt * 16 + grp;
            size_t o0 = (size_t)row0 * NCOLS + col;
            size_t o1 = o0 + ((size_t)8 * NCOLS);
            float2 v0 = make_float2(c[mt][nt][0], c[mt][nt][1]);
            float2 v1 = make_float2(c[mt][nt][2], c[mt][nt][3]);
            if (MODE == 1) {
                float2 x0 = *(const float2*)(xres + o0);
                float2 x1 = *(const float2*)(xres + o1);
                v0.x += d.x * x0.x; v0.y += d.y * x0.y;
                v1.x += d.x * x1.x; v1.y += d.y * x1.y;
            }
            *(float2*)(Cout + o0) = v0;
            *(float2*)(Cout + o1) = v1;
        }
    }
}

// ---------------------------------------------------------------------------
// Scan pass 1: chunk-local scans with zero init; store final (z1,z2)
// ---------------------------------------------------------------------------
__global__ void __launch_bounds__(256) scan_pass1() {
    int c = blockIdx.x, b = blockIdx.y, z = blockIdx.z;
    int p = threadIdx.x;
    int n = (z << 8) + p;
    int sid = (b << 9) + n;

    float s1  = g_cf[p * 8 + 0];
    float s2  = g_cf[p * 8 + 1];
    float c12 = g_cf[p * 8 + 2];
    float c21 = g_cf[p * 8 + 3];
    float c22 = g_cf[p * 8 + 4];

    size_t base = ((size_t)(b * LSEQ + c * TCH) << 9) + n;
    float z1 = 0.0f, z2 = 0.0f;
    #pragma unroll 8
    for (int i = 0; i < TCH; i++) {
        float bu = g_Bu[base + ((size_t)i << 9)];
        float nz1 = fmaf(c12, z2, fmaf(s1, bu, z1));
        float nz2 = fmaf(c21, z1, fmaf(c22, z2, s2 * bu));
        z1 = nz1; z2 = nz2;
    }
    g_loc1[c * NSEQ + sid] = z1;
    g_loc2[c * NSEQ + sid] = z2;
}

// ---------------------------------------------------------------------------
// Scan pass 2: sequential carry scan across chunks (exclusive carries)
// ---------------------------------------------------------------------------
__global__ void __launch_bounds__(256) scan_pass2() {
    int sid = blockIdx.x * 256 + threadIdx.x;   // 0..4095
    int p = sid & 255;
    float m11 = g_mp[p * 4 + 0];
    float m12 = g_mp[p * 4 + 1];
    float m21 = g_mp[p * 4 + 2];
    float m22 = g_mp[p * 4 + 3];

    float c1 = 0.0f, c2 = 0.0f;
    for (int c = 0; c < NCH; c++) {
        g_car1[c * NSEQ + sid] = c1;
        g_car2[c * NSEQ + sid] = c2;
        float l1 = g_loc1[c * NSEQ + sid];
        float l2 = g_loc2[c * NSEQ + sid];
        float n1 = fmaf(m11, c1, fmaf(m12, c2, l1));
        float n2 = fmaf(m21, c1, fmaf(m22, c2, l2));
        c1 = n1; c2 = n2;
    }
}

// ---------------------------------------------------------------------------
// Scan pass 3: replay with carry-in, emit ys as fp16
// ---------------------------------------------------------------------------
__global__ void __launch_bounds__(256) scan_pass3() {
    int c = blockIdx.x, b = blockIdx.y, z = blockIdx.z;
    int p = threadIdx.x;
    int n = (z << 8) + p;
    int sid = (b << 9) + n;

    float s1  = g_cf[p * 8 + 0];
    float s2  = g_cf[p * 8 + 1];
    float c12 = g_cf[p * 8 + 2];
    float c21 = g_cf[p * 8 + 3];
    float c22 = g_cf[p * 8 + 4];

    size_t base = ((size_t)(b * LSEQ + c * TCH) << 9) + n;
    float z1 = g_car1[c * NSEQ + sid];
    float z2 = g_car2[c * NSEQ + sid];
    #pragma unroll 8
    for (int i = 0; i < TCH; i++) {
        float bu = g_Bu[base + ((size_t)i << 9)];
        float nz1 = fmaf(c12, z2, fmaf(s1, bu, z1));
        float nz2 = fmaf(c21, z1, fmaf(c22, z2, s2 * bu));
        z1 = nz1; z2 = nz2;
        g_ysf[base + ((size_t)i << 9)] = __float2half(z2);
    }
}

// ---------------------------------------------------------------------------
// Launch
// ---------------------------------------------------------------------------
extern "C" void kernel_launch(void* const* d_in, const int* in_sizes, int n_in,
                              void* d_out, int out_size) {
    const float* x  = (const float*)d_in[0];   // (8, 8192, 512)
    const float* sp = (const float*)d_in[1];   // (256,)
    const float* Ap = (const float*)d_in[2];   // (256,)
    const float* Bp = (const float*)d_in[3];   // (256, 512, 2)
    const float* Cp = (const float*)d_in[4];   // (512, 256, 2)
    const float* Dp = (const float*)d_in[5];   // (512,)
    float* y = (float*)d_out;                  // (8, 8192, 512)

    cudaFuncSetAttribute(mma_gemm<0>, cudaFuncAttributeMaxDynamicSharedMemorySize, SM_TOTAL);
    cudaFuncSetAttribute(mma_gemm<1>, cudaFuncAttributeMaxDynamicSharedMemorySize, SM_TOTAL);

    prep_kernel<<<1, 256>>>(sp, Ap);
    buildW_kernel<<<1024, 256>>>(Bp, Cp);
    convX_kernel<<<(MROWS * NCOLS) / 1024, 256>>>(x);

    // GEMM1: Bu = x @ W1
    mma_gemm<0><<<dim3(NCOLS / BN, MROWS / BM), 256, SM_TOTAL>>>(nullptr, nullptr, nullptr);

    // Chunked linear scan (pass3 emits ys as fp16)
    scan_pass1<<<dim3(NCH, BT, 2), 256>>>();
    scan_pass2<<<16, 256>>>();
    scan_pass3<<<dim3(NCH, BT, 2), 256>>>();

    // GEMM2 + epilogue: y = ys @ W2 + D .* x
    mma_gemm<1><<<dim3(NCOLS / BN, MROWS / BM), 256, SM_TOTAL>>>(y, x, Dp);
}

// round 14
// speedup vs baseline: 2.2416x; 1.0794x over previous
#include <cuda_runtime.h>
#include <cuda_bf16.h>
#include <cuda_fp16.h>
#include <math.h>
#include <stdint.h>

// R14: two traffic/overhead cuts on the R13 design (439.9us, rel_err 4.17e-4):
//  (a) Bu stored fp16 (GEMM1 out + scan in): -190MB traffic, adds one 2^-11
//      rounding -> predicted total ~5.1e-4 vs 1e-3 budget.
//  (b) BK=64 / SW128 stages (ported from R7's verified layout): 8 stages
//      instead of 16 -> half the sync/wait overhead per GEMM.
// Keeps: single-fp16 MMA (1 term), 3-stage cp.async ring, 2 CTAs/SM.

// Problem constants
#define BT    8
#define LSEQ  8192
#define HID   512
#define PDIM  256
#define MROWS (BT * LSEQ)     // 65536 tokens
#define NCOLS 512             // 2*P (re | im)
#define KDIM  512
#define NCH   64              // scan chunks
#define TCH   128             // steps per chunk
#define NSEQ  (BT * 512)      // 4096 independent real 2-state scans

// GEMM tiling
#define BM 128
#define BN 128
#define BK 64                 // 128 B of fp16 per row -> SW128 swizzle
#define NK (KDIM / BK)        // 8 k-stages

// SMEM: 3 stages x 32KB. Per stage: Af 16K | Wf 16K
#define STG_BYTES 32768
#define SM_TOTAL  (3 * STG_BYTES)

// ---------------------------------------------------------------------------
// Static device scratch
// ---------------------------------------------------------------------------
__device__ __half g_W1f[KDIM * NCOLS];          // [n][k] fp16
__device__ __half g_W2f[KDIM * NCOLS];
__device__ __half g_xf[(size_t)MROWS * NCOLS];  // x fp16
__device__ __half g_Buh[(size_t)MROWS * NCOLS]; // Bu fp16 (64 MB)
__device__ __half g_ysf[(size_t)MROWS * NCOLS]; // ys fp16 (64 MB)
__device__ float g_cf[PDIM * 8];
__device__ float g_mp[PDIM * 4];
__device__ float g_loc1[NCH * NSEQ];
__device__ float g_loc2[NCH * NSEQ];
__device__ float g_car1[NCH * NSEQ];
__device__ float g_car2[NCH * NSEQ];

// ---------------------------------------------------------------------------
// helpers
// ---------------------------------------------------------------------------
__device__ __forceinline__ uint32_t smem_u32(const void* p) {
    uint32_t a;
    asm("{ .reg .u64 t; cvta.to.shared.u64 t, %1; cvt.u32.u64 %0, t; }" : "=r"(a) : "l"(p));
    return a;
}
__device__ __forceinline__ void cp_async16(uint32_t dst, const void* src) {
    asm volatile("cp.async.cg.shared.global [%0], [%1], 16;" :: "r"(dst), "l"(src) : "memory");
}
__device__ __forceinline__ void cp_commit() {
    asm volatile("cp.async.commit_group;" ::: "memory");
}
template <int N>
__device__ __forceinline__ void cp_wait() {
    asm volatile("cp.async.wait_group %0;" :: "n"(N) : "memory");
}
__device__ __forceinline__ void ldsm_x4(uint32_t* r, uint32_t addr) {
    asm volatile("ldmatrix.sync.aligned.m8n8.x4.shared.b16 {%0,%1,%2,%3}, [%4];"
                 : "=r"(r[0]), "=r"(r[1]), "=r"(r[2]), "=r"(r[3]) : "r"(addr));
}
__device__ __forceinline__ void mma_f16(float* c, const uint32_t* a, uint32_t b0, uint32_t b1) {
    asm volatile(
        "mma.sync.aligned.m16n8k16.row.col.f32.f16.f16.f32 "
        "{%0,%1,%2,%3}, {%4,%5,%6,%7}, {%8,%9}, {%0,%1,%2,%3};\n"
        : "+f"(c[0]), "+f"(c[1]), "+f"(c[2]), "+f"(c[3])
        : "r"(a[0]), "r"(a[1]), "r"(a[2]), "r"(a[3]), "r"(b0), "r"(b1));
}
__device__ __forceinline__ uint32_t pack_h(__half a, __half b) {
    return (uint32_t)__half_as_ushort(a) | ((uint32_t)__half_as_ushort(b) << 16);
}

// ---------------------------------------------------------------------------
// Kernel 0: per-p coefficients + M^TCH
// ---------------------------------------------------------------------------
__global__ void prep_kernel(const float* __restrict__ steps_param,
                            const float* __restrict__ A_param) {
    int p = threadIdx.x;
    float s = 1.0f / (1.0f + expf(-steps_param[p]));
    float a = fmaxf(A_param[p], 0.0f);
    float c12 = -s * a;
    float c21 = s;
    float c22 = 1.0f - s * s * a;
    g_cf[p * 8 + 0] = s;
    g_cf[p * 8 + 1] = s * s;
    g_cf[p * 8 + 2] = c12;
    g_cf[p * 8 + 3] = c21;
    g_cf[p * 8 + 4] = c22;

    float ma = 1.0f, mb = c12, mc = c21, md = c22;
    #pragma unroll
    for (int i = 0; i < 7; i++) {
        float na = ma * ma + mb * mc;
        float nb = ma * mb + mb * md;
        float nc = mc * ma + md * mc;
        float nd = mc * mb + md * md;
        ma = na; mb = nb; mc = nc; md = nd;
    }
    g_mp[p * 4 + 0] = ma;
    g_mp[p * 4 + 1] = mb;
    g_mp[p * 4 + 2] = mc;
    g_mp[p * 4 + 3] = md;
}

// ---------------------------------------------------------------------------
// Kernel 1: pack weights into [n][k] fp16
// ---------------------------------------------------------------------------
__global__ void buildW_kernel(const float* __restrict__ Bp,
                              const float* __restrict__ Cp) {
    int idx = blockIdx.x * 256 + threadIdx.x;   // 0 .. 512*512-1
    {
        int k = idx >> 9;
        int n = idx & 511;
        float v = (n < 256) ? Bp[n * (HID * 2) + k * 2 + 0]
                            : Bp[(n - 256) * (HID * 2) + k * 2 + 1];
        g_W1f[n * KDIM + k] = __float2half(v);
    }
    {
        int k = idx >> 9;
        int n = idx & 511;
        float v = (k < 256) ? Cp[n * (PDIM * 2) + k * 2 + 0]
                            : -Cp[n * (PDIM * 2) + (k - 256) * 2 + 1];
        g_W2f[n * KDIM + k] = __float2half(v);
    }
}

// ---------------------------------------------------------------------------
// Kernel 2: convert x to fp16
// ---------------------------------------------------------------------------
__global__ void __launch_bounds__(256) convX_kernel(const float* __restrict__ x) {
    size_t i = ((size_t)blockIdx.x * 256 + threadIdx.x) << 2;
    float4 v = *(const float4*)(x + i);
    *(uint2*)(g_xf + i) = make_uint2(pack_h(__float2half(v.x), __float2half(v.y)),
                                     pack_h(__float2half(v.z), __float2half(v.w)));
}

// ---------------------------------------------------------------------------
// mma.sync fp16 GEMM (single term), 3-stage cp.async ring, SW128, ldmatrix.
// 128x128 block, K stages of 64, 256 thr = 8 warps (2m x 4n), warp 64x32.
// MODE 0: out fp16 g_Buh.  MODE 1: out fp32 y with + D.*x epilogue.
// ---------------------------------------------------------------------------
template <int MODE>
__global__ void __launch_bounds__(256, 2)
mma_gemm(float* __restrict__ Cext, const float* __restrict__ xres,
         const float* __restrict__ Dv) {
    extern __shared__ __align__(128) char smem[];
    const uint32_t sb = smem_u32(smem);

    const __half* Af = (MODE == 0) ? g_xf : g_ysf;
    const __half* Wf = (MODE == 0) ? g_W1f : g_W2f;

    const int tid  = threadIdx.x;
    const int lane = tid & 31;
    const int wid  = tid >> 5;
    const int warp_m = wid & 1;        // 0..1 -> 64 rows
    const int warp_n = wid >> 1;       // 0..3 -> 32 cols
    const int mBase = blockIdx.y << 7;
    const int nBase = blockIdx.x << 7;

    // ldmatrix lane mapping
    const int rl   = (lane & 7) + ((lane >> 3) & 1) * 8;
    const int kq16 = (lane >> 4) << 4;

    uint32_t aOff[4], aXor[4];
    #pragma unroll
    for (int mt = 0; mt < 4; mt++) {
        int row = warp_m * 64 + mt * 16 + rl;
        aOff[mt] = row << 7;
        aXor[mt] = (row & 7) << 4;      // SW128: d ^ ((d>>3)&0x70)
    }
    uint32_t bOff[2], bXor[2];
    #pragma unroll
    for (int g = 0; g < 2; g++) {
        int row = warp_n * 32 + g * 16 + rl;
        bOff[g] = row << 7;
        bXor[g] = (row & 7) << 4;
    }

    float c[4][4][4];
    #pragma unroll
    for (int mt = 0; mt < 4; mt++)
        #pragma unroll
        for (int nt = 0; nt < 4; nt++)
            #pragma unroll
            for (int r = 0; r < 4; r++) c[mt][nt][r] = 0.0f;

    // ---- stage loader: 2 matrices x 128 rows x 8 segs(16B) = 2048 cp.async ----
    auto load_stage = [&](int kc, int buf) {
        const uint32_t s0 = sb + buf * STG_BYTES;
        const int k0 = kc * BK;
        #pragma unroll
        for (int it = 0; it < 8; it++) {
            int lin = tid + (it << 8);     // 0..2047
            int mat = lin >> 10;           // constant per it
            int l2  = lin & 1023;
            int r   = l2 >> 3;             // row 0..127
            int s   = l2 & 7;              // 16B seg 0..7
            uint32_t d = (r << 7) + (s << 4);
            d ^= (d >> 3) & 0x70;          // SW128
            const __half* src = (mat == 0) ? Af : Wf;
            int rowg = ((mat == 0) ? mBase : nBase) + r;
            cp_async16(s0 + mat * 16384 + d, src + (size_t)rowg * KDIM + k0 + (s << 3));
        }
        cp_commit();
    };

    load_stage(0, 0);
    load_stage(1, 1);

    int buf = 0;
    for (int kc = 0; kc < NK; kc++) {
        cp_wait<1>();
        __syncthreads();

        if (kc + 2 < NK) {
            int nb = buf + 2; if (nb >= 3) nb -= 3;
            load_stage(kc + 2, nb);
        } else {
            cp_commit();
        }

        const uint32_t s0 = sb + buf * STG_BYTES;
        const uint32_t aFf = s0, bFf = s0 + 16384;

        #pragma unroll
        for (int ks = 0; ks < 4; ks++) {
            const uint32_t kb = (ks << 5) + kq16;
            uint32_t ah[4][4];
            #pragma unroll
            for (int mt = 0; mt < 4; mt++)
                ldsm_x4(ah[mt], aFf + aOff[mt] + (kb ^ aXor[mt]));
            #pragma unroll
            for (int g = 0; g < 2; g++) {
                uint32_t bf[4];
                ldsm_x4(bf, bFf + bOff[g] + (kb ^ bXor[g]));
                #pragma unroll
                for (int n2 = 0; n2 < 2; n2++) {
                    const int nt = g * 2 + n2;
                    const uint32_t b0 = bf[n2], b1 = bf[n2 + 2];
                    #pragma unroll
                    for (int mt = 0; mt < 4; mt++)
                        mma_f16(c[mt][nt], ah[mt], b0, b1);
                }
            }
        }
        if (++buf == 3) buf = 0;
    }

    // ---- epilogue ----
    const int grp = lane >> 2;
    const int tig = lane & 3;
    #pragma unroll
    for (int nt = 0; nt < 4; nt++) {
        int col = nBase + warp_n * 32 + nt * 8 + (tig << 1);
        float2 d;
        if (MODE == 1) d = *(const float2*)(Dv + col);
        #pragma unroll
        for (int mt = 0; mt < 4; mt++) {
            int row0 = mBase + warp_m * 64 + mt * 16 + grp;
            size_t o0 = (size_t)row0 * NCOLS + col;
            size_t o1 = o0 + ((size_t)8 * NCOLS);
            if (MODE == 1) {
                float2 x0 = *(const float2*)(xres + o0);
                float2 x1 = *(const float2*)(xres + o1);
                float2 v0 = make_float2(c[mt][nt][0] + d.x * x0.x,
                                        c[mt][nt][1] + d.y * x0.y);
                float2 v1 = make_float2(c[mt][nt][2] + d.x * x1.x,
                                        c[mt][nt][3] + d.y * x1.y);
                *(float2*)(Cext + o0) = v0;
                *(float2*)(Cext + o1) = v1;
            } else {
                *(uint32_t*)(g_Buh + o0) =
                    pack_h(__float2half(c[mt][nt][0]), __float2half(c[mt][nt][1]));
                *(uint32_t*)(g_Buh + o1) =
                    pack_h(__float2half(c[mt][nt][2]), __float2half(c[mt][nt][3]));
            }
        }
    }
}

// ---------------------------------------------------------------------------
// Scan pass 1: chunk-local scans with zero init; store final (z1,z2)
// ---------------------------------------------------------------------------
__global__ void __launch_bounds__(256) scan_pass1() {
    int c = blockIdx.x, b = blockIdx.y, z = blockIdx.z;
    int p = threadIdx.x;
    int n = (z << 8) + p;
    int sid = (b << 9) + n;

    float s1  = g_cf[p * 8 + 0];
    float s2  = g_cf[p * 8 + 1];
    float c12 = g_cf[p * 8 + 2];
    float c21 = g_cf[p * 8 + 3];
    float c22 = g_cf[p * 8 + 4];

    size_t base = ((size_t)(b * LSEQ + c * TCH) << 9) + n;
    float z1 = 0.0f, z2 = 0.0f;
    #pragma unroll 8
    for (int i = 0; i < TCH; i++) {
        float bu = __half2float(g_Buh[base + ((size_t)i << 9)]);
        float nz1 = fmaf(c12, z2, fmaf(s1, bu, z1));
        float nz2 = fmaf(c21, z1, fmaf(c22, z2, s2 * bu));
        z1 = nz1; z2 = nz2;
    }
    g_loc1[c * NSEQ + sid] = z1;
    g_loc2[c * NSEQ + sid] = z2;
}

// ---------------------------------------------------------------------------
// Scan pass 2: sequential carry scan across chunks (exclusive carries)
// ---------------------------------------------------------------------------
__global__ void __launch_bounds__(256) scan_pass2() {
    int sid = blockIdx.x * 256 + threadIdx.x;   // 0..4095
    int p = sid & 255;
    float m11 = g_mp[p * 4 + 0];
    float m12 = g_mp[p * 4 + 1];
    float m21 = g_mp[p * 4 + 2];
    float m22 = g_mp[p * 4 + 3];

    float c1 = 0.0f, c2 = 0.0f;
    for (int c = 0; c < NCH; c++) {
        g_car1[c * NSEQ + sid] = c1;
        g_car2[c * NSEQ + sid] = c2;
        float l1 = g_loc1[c * NSEQ + sid];
        float l2 = g_loc2[c * NSEQ + sid];
        float n1 = fmaf(m11, c1, fmaf(m12, c2, l1));
        float n2 = fmaf(m21, c1, fmaf(m22, c2, l2));
        c1 = n1; c2 = n2;
    }
}

// ---------------------------------------------------------------------------
// Scan pass 3: replay with carry-in, emit ys as fp16
// ---------------------------------------------------------------------------
__global__ void __launch_bounds__(256) scan_pass3() {
    int c = blockIdx.x, b = blockIdx.y, z = blockIdx.z;
    int p = threadIdx.x;
    int n = (z << 8) + p;
    int sid = (b << 9) + n;

    float s1  = g_cf[p * 8 + 0];
    float s2  = g_cf[p * 8 + 1];
    float c12 = g_cf[p * 8 + 2];
    float c21 = g_cf[p * 8 + 3];
    float c22 = g_cf[p * 8 + 4];

    size_t base = ((size_t)(b * LSEQ + c * TCH) << 9) + n;
    float z1 = g_car1[c * NSEQ + sid];
    float z2 = g_car2[c * NSEQ + sid];
    #pragma unroll 8
    for (int i = 0; i < TCH; i++) {
        float bu = __half2float(g_Buh[base + ((size_t)i << 9)]);
        float nz1 = fmaf(c12, z2, fmaf(s1, bu, z1));
        float nz2 = fmaf(c21, z1, fmaf(c22, z2, s2 * bu));
        z1 = nz1; z2 = nz2;
        g_ysf[base + ((size_t)i << 9)] = __float2half(z2);
    }
}

// ---------------------------------------------------------------------------
// Launch
// ---------------------------------------------------------------------------
extern "C" void kernel_launch(void* const* d_in, const int* in_sizes, int n_in,
                              void* d_out, int out_size) {
    const float* x  = (const float*)d_in[0];   // (8, 8192, 512)
    const float* sp = (const float*)d_in[1];   // (256,)
    const float* Ap = (const float*)d_in[2];   // (256,)
    const float* Bp = (const float*)d_in[3];   // (256, 512, 2)
    const float* Cp = (const float*)d_in[4];   // (512, 256, 2)
    const float* Dp = (const float*)d_in[5];   // (512,)
    float* y = (float*)d_out;                  // (8, 8192, 512)

    cudaFuncSetAttribute(mma_gemm<0>, cudaFuncAttributeMaxDynamicSharedMemorySize, SM_TOTAL);
    cudaFuncSetAttribute(mma_gemm<1>, cudaFuncAttributeMaxDynamicSharedMemorySize, SM_TOTAL);

    prep_kernel<<<1, 256>>>(sp, Ap);
    buildW_kernel<<<1024, 256>>>(Bp, Cp);
    convX_kernel<<<(MROWS * NCOLS) / 1024, 256>>>(x);

    // GEMM1: Bu(fp16) = x @ W1
    mma_gemm<0><<<dim3(NCOLS / BN, MROWS / BM), 256, SM_TOTAL>>>(nullptr, nullptr, nullptr);

    // Chunked linear scan (pass3 emits ys as fp16)
    scan_pass1<<<dim3(NCH, BT, 2), 256>>>();
    scan_pass2<<<16, 256>>>();
    scan_pass3<<<dim3(NCH, BT, 2), 256>>>();

    // GEMM2 + epilogue: y = ys @ W2 + D .* x
    mma_gemm<1><<<dim3(NCOLS / BN, MROWS / BM), 256, SM_TOTAL>>>(y, x, Dp);
}